// round 2
// baseline (speedup 1.0000x reference)
#include <cuda_runtime.h>
#include <cuda_bf16.h>

#define TT    100000
#define HDIM  16
#define UDIM  7
#define HID   64
#define XDIM  (HDIM + UDIM)

typedef unsigned long long u64;

// Scratch (static device globals — no runtime allocation).
__device__ float g_V[(TT + 1) * HID];        // V[t][j] = b1[j] + W1_u[j] . u_t
__device__ float g_htraj[(TT + 1) * HDIM];   // h_t trajectory

// ---------------- packed f32x2 helpers (sm_103a) ----------------
__device__ __forceinline__ u64 pk2(float lo, float hi) {
    u64 r; asm("mov.b64 %0, {%1,%2};" : "=l"(r) : "f"(lo), "f"(hi)); return r;
}
__device__ __forceinline__ float2 upk2(u64 v) {
    float2 f; asm("mov.b64 {%0,%1}, %2;" : "=f"(f.x), "=f"(f.y) : "l"(v)); return f;
}
__device__ __forceinline__ u64 ffma2(u64 a, u64 b, u64 c) {
    u64 d; asm("fma.rn.f32x2 %0, %1, %2, %3;" : "=l"(d) : "l"(a), "l"(b), "l"(c)); return d;
}
__device__ __forceinline__ u64 fadd2(u64 a, u64 b) {
    u64 d; asm("add.rn.f32x2 %0, %1, %2;" : "=l"(d) : "l"(a), "l"(b)); return d;
}

// branchless accurate-enough tanh: 1 - 2/(e^{2x}+1).  2 MUFU + 3 flops, ~1e-6 rel err.
__device__ __forceinline__ float fast_tanh(float x) {
    float e;
    asm("ex2.approx.f32 %0, %1;" : "=f"(e) : "f"(x * 2.8853900817779268f)); // 2*log2(e)
    float r;
    asm("rcp.approx.f32 %0, %1;" : "=f"(r) : "f"(e + 1.0f));
    return fmaf(-2.0f, r, 1.0f);
}

// ---------------------------------------------------------------------------
// Kernel 1: V[t][j] = b1[j] + W1_u[j] . u_t   (parallel over t)
// ---------------------------------------------------------------------------
__global__ void pre_kernel(const float* __restrict__ U,
                           const float* __restrict__ W1,
                           const float* __restrict__ b1) {
    int j = threadIdx.x;
    int t = blockIdx.x * blockDim.y + threadIdx.y;
    if (t >= TT) return;
    float acc = b1[j];
    const float* u = U + t * UDIM;
    const float* w = W1 + j * XDIM + HDIM;
#pragma unroll
    for (int c = 0; c < UDIM; c++)
        acc += w[c] * __ldg(u + c);
    g_V[t * HID + j] = acc;
}

// ---------------------------------------------------------------------------
// Kernel 2: sequential scan. 1 CTA, 64 threads (2 warps). All math f32x2-packed.
// ---------------------------------------------------------------------------
__global__ void __launch_bounds__(64, 1)
scan_kernel(const float* __restrict__ W1,
            const float* __restrict__ W2,
            const float* __restrict__ b2,
            const float* __restrict__ W3,
            const float* __restrict__ b3,
            const float* __restrict__ h0,
            float* __restrict__ out) {
    const int j = threadIdx.x;

    __shared__ __align__(16) float z1s[HID];
    __shared__ __align__(16) float z2s[HID];
    __shared__ __align__(16) float hs[HDIM];

    const float dt = (float)(5.0 / 60.0);

    // ---- packed weights in registers ----
    u64 w1h[8];                                   // W1[:, 0:16] row j
#pragma unroll
    for (int c = 0; c < 8; c++)
        w1h[c] = pk2(W1[j * XDIM + 2 * c], W1[j * XDIM + 2 * c + 1]);

    u64 w2p[32];                                  // W2 row j
#pragma unroll
    for (int c = 0; c < 32; c++)
        w2p[c] = pk2(W2[j * HID + 2 * c], W2[j * HID + 2 * c + 1]);
    const float b2j = b2[j];

    // dh tasks live on warp 0: lane j<32, output i = j>>1, half = j&1,
    // covering dt*W3[i, half*32 : half*32+32].
    const int i    = (j & 31) >> 1;
    const int half = j & 1;
    u64 w3p[16];
#pragma unroll
    for (int m = 0; m < 16; m++)
        w3p[m] = pk2(dt * W3[i * HID + half * 32 + 2 * m],
                     dt * W3[i * HID + half * 32 + 2 * m + 1]);
    const float b3i = (half == 0) ? dt * b3[i] : 0.0f;

    // packed hidden state (replicated per lane)
    u64 hp[8];
#pragma unroll
    for (int c = 0; c < 8; c++)
        hp[c] = pk2(h0[2 * c], h0[2 * c + 1]);

    if (j < HDIM) { g_htraj[j] = h0[j]; hs[j] = h0[j]; }

    float vcur = g_V[j];
    const float* vp = g_V + HID + j;

#pragma unroll 1
    for (int t = 0; t < TT; t++) {
        float vnext = __ldg(vp);                  // consumed next iteration
        vp += HID;

        // ---- z1 = tanh(W1_h . h + V[t]) ----
        u64 a0 = pk2(vcur, 0.0f), a1 = 0ull, a2 = 0ull, a3 = 0ull;
        a0 = ffma2(w1h[0], hp[0], a0);
        a1 = ffma2(w1h[1], hp[1], a1);
        a2 = ffma2(w1h[2], hp[2], a2);
        a3 = ffma2(w1h[3], hp[3], a3);
        a0 = ffma2(w1h[4], hp[4], a0);
        a1 = ffma2(w1h[5], hp[5], a1);
        a2 = ffma2(w1h[6], hp[6], a2);
        a3 = ffma2(w1h[7], hp[7], a3);
        {
            float2 s = upk2(fadd2(fadd2(a0, a1), fadd2(a2, a3)));
            z1s[j] = fast_tanh(s.x + s.y);
        }
        __syncthreads();

        // ---- z2 = tanh(W2 . z1 + b2) ----
        u64 c0 = pk2(b2j, 0.0f), c1 = 0ull, c2 = 0ull, c3 = 0ull;
        const ulonglong2* z14 = (const ulonglong2*)z1s;
#pragma unroll
        for (int c = 0; c < 16; c += 2) {
            ulonglong2 za = z14[c];
            ulonglong2 zb = z14[c + 1];
            c0 = ffma2(w2p[2 * c + 0], za.x, c0);
            c1 = ffma2(w2p[2 * c + 1], za.y, c1);
            c2 = ffma2(w2p[2 * c + 2], zb.x, c2);
            c3 = ffma2(w2p[2 * c + 3], zb.y, c3);
        }
        {
            float2 s = upk2(fadd2(fadd2(c0, c1), fadd2(c2, c3)));
            z2s[j] = fast_tanh(s.x + s.y);
        }
        __syncthreads();

        // ---- dh (warp 0 only): p = dt*W3[i, half].z2_half, combine halves ----
        if (j < 32) {
            const ulonglong2* zz = (const ulonglong2*)(z2s + half * 32);
            u64 p0 = 0ull, p1 = 0ull, p2 = 0ull, p3 = 0ull;
#pragma unroll
            for (int m = 0; m < 8; m += 2) {
                ulonglong2 za = zz[m];
                ulonglong2 zb = zz[m + 1];
                p0 = ffma2(w3p[2 * m + 0], za.x, p0);
                p1 = ffma2(w3p[2 * m + 1], za.y, p1);
                p2 = ffma2(w3p[2 * m + 2], zb.x, p2);
                p3 = ffma2(w3p[2 * m + 3], zb.y, p3);
            }
            float2 s = upk2(fadd2(fadd2(p0, p1), fadd2(p2, p3)));
            float p = (s.x + s.y) + b3i;
            p += __shfl_xor_sync(0xffffffffu, p, 1);
            if (half == 0) {
                float2 hv = upk2(hp[i >> 1]);
                float hold = (i & 1) ? hv.y : hv.x;
                float hn = hold + p;
                hs[i] = hn;
                g_htraj[(t + 1) * HDIM + i] = hn;  // fire-and-forget
            }
        }
        __syncthreads();

        // ---- reload packed h ----
        {
            const ulonglong2* h4 = (const ulonglong2*)hs;
            ulonglong2 A = h4[0], B = h4[1], C = h4[2], D = h4[3];
            hp[0] = A.x; hp[1] = A.y;
            hp[2] = B.x; hp[3] = B.y;
            hp[4] = C.x; hp[5] = C.y;
            hp[6] = D.x; hp[7] = D.y;
        }
        vcur = vnext;
    }

    if (j < HDIM) out[3 * TT + j] = hs[j];
}

// ---------------------------------------------------------------------------
// Kernel 3: readouts (parallel over t)
// ---------------------------------------------------------------------------
__global__ void readout_kernel(const float* __restrict__ wd, const float* __restrict__ bd,
                               const float* __restrict__ wt, const float* __restrict__ bt,
                               const float* __restrict__ wc, const float* __restrict__ bc,
                               float* __restrict__ out) {
    int t = blockIdx.x * blockDim.x + threadIdx.x;
    if (t >= TT) return;

    float vd[HDIM], vt[HDIM], vc[HDIM];
#pragma unroll
    for (int k = 0; k < HDIM; k++) {
        vd[k] = __ldg(wd + k);
        vt[k] = __ldg(wt + k);
        vc[k] = __ldg(wc + k);
    }
    float d = __ldg(bd), x = __ldg(bt), c = __ldg(bc);
    const float4* h4 = (const float4*)(g_htraj + t * HDIM);
#pragma unroll
    for (int k = 0; k < 4; k++) {
        float4 hv = h4[k];
        d += hv.x * vd[4 * k] + hv.y * vd[4 * k + 1] + hv.z * vd[4 * k + 2] + hv.w * vd[4 * k + 3];
        x += hv.x * vt[4 * k] + hv.y * vt[4 * k + 1] + hv.z * vt[4 * k + 2] + hv.w * vt[4 * k + 3];
        c += hv.x * vc[4 * k] + hv.y * vc[4 * k + 1] + hv.z * vc[4 * k + 2] + hv.w * vc[4 * k + 3];
    }
    out[t]          = d;
    out[TT + t]     = x;
    out[2 * TT + t] = c;
}

// ---------------------------------------------------------------------------
extern "C" void kernel_launch(void* const* d_in, const int* in_sizes, int n_in,
                              void* d_out, int out_size) {
    const float* U  = (const float*)d_in[0];
    const float* W1 = (const float*)d_in[1];
    const float* b1 = (const float*)d_in[2];
    const float* W2 = (const float*)d_in[3];
    const float* b2 = (const float*)d_in[4];
    const float* W3 = (const float*)d_in[5];
    const float* b3 = (const float*)d_in[6];
    const float* wd = (const float*)d_in[7];
    const float* bd = (const float*)d_in[8];
    const float* wt = (const float*)d_in[9];
    const float* bt = (const float*)d_in[10];
    const float* wc = (const float*)d_in[11];
    const float* bc = (const float*)d_in[12];
    const float* h0 = (const float*)d_in[13];
    float* out = (float*)d_out;

    dim3 pb(HID, 4);
    pre_kernel<<<(TT + 3) / 4, pb>>>(U, W1, b1);
    scan_kernel<<<1, HID>>>(W1, W2, b2, W3, b3, h0, out);
    readout_kernel<<<(TT + 127) / 128, 128>>>(wd, bd, wt, bt, wc, bc, out);
}

// round 3
// speedup vs baseline: 1.1639x; 1.1639x over previous
#include <cuda_runtime.h>
#include <cuda_bf16.h>

#define TT    100000
#define HDIM  16
#define UDIM  7
#define HID   64
#define XDIM  (HDIM + UDIM)
#define CHUNK 1024
#define NB    ((TT + CHUNK - 1) / CHUNK)   // 98

// ---- static device scratch (no runtime allocation) ----
__device__ float g_DV[(TT + 1) * HID];   // DV_t ; row TT never written (stays 0)
__device__ float g_M[HID * HID];         // dt * W1h @ W3
__device__ float g_R[3 * HID];           // rd, rt, rc = dt * W3^T w{d,t,c}
__device__ float g_C[3];                 // dt * (b3 . w)
__device__ float g_base[3];              // h0 . w + bias
__device__ float g_z2[TT * HID];         // z2 trajectory
__device__ float g_sumz2[HID];           // sum_t z2_t
__device__ float g_scan[3][TT];          // in-block exclusive scans
__device__ float g_btot[3][NB];
__device__ float g_boff[3][NB];

__device__ __forceinline__ float fast_tanh(float x) {
    float e;
    asm("ex2.approx.f32 %0, %1;" : "=f"(e) : "f"(x * 2.8853900817779268f));
    float r;
    asm("rcp.approx.f32 %0, %1;" : "=f"(r) : "f"(e + 1.0f));
    return fmaf(-2.0f, r, 1.0f);
}

// ---------------------------------------------------------------------------
// Kernel 1: constants — M, R vectors, C, base, zero g_sumz2
// grid 16 x 256
// ---------------------------------------------------------------------------
__global__ void const_kernel(const float* __restrict__ W1,
                             const float* __restrict__ W3,
                             const float* __restrict__ b3,
                             const float* __restrict__ wd, const float* __restrict__ bd,
                             const float* __restrict__ wt, const float* __restrict__ bt,
                             const float* __restrict__ wc, const float* __restrict__ bc,
                             const float* __restrict__ h0) {
    const float dt = (float)(5.0 / 60.0);
    int idx = blockIdx.x * blockDim.x + threadIdx.x;
    if (idx < HID * HID) {
        int r = idx >> 6, c = idx & 63;
        float s = 0.0f;
#pragma unroll
        for (int k = 0; k < HDIM; k++)
            s += W1[r * XDIM + k] * W3[k * HID + c];
        g_M[idx] = dt * s;
    }
    if (blockIdx.x == 0) {
        int tid = threadIdx.x;
        if (tid < 3 * HID) {
            int s = tid >> 6, c = tid & 63;
            const float* w = (s == 0) ? wd : (s == 1) ? wt : wc;
            float acc = 0.0f;
#pragma unroll
            for (int i = 0; i < HDIM; i++)
                acc += W3[i * HID + c] * w[i];
            g_R[tid] = dt * acc;
        }
        if (tid < HID) g_sumz2[tid] = 0.0f;
        if (tid < 3) {
            const float* w = (tid == 0) ? wd : (tid == 1) ? wt : wc;
            float cb = 0.0f, ba = 0.0f;
#pragma unroll
            for (int i = 0; i < HDIM; i++) { cb += b3[i] * w[i]; ba += h0[i] * w[i]; }
            g_C[tid] = dt * cb;
            g_base[tid] = ba + ((tid == 0) ? *bd : (tid == 1) ? *bt : *bc);
        }
    }
}

// ---------------------------------------------------------------------------
// Kernel 2: DV_t[j] = W1u[j].(u_{t+1}-u_t) + dt*(W1h[j].b3)   (parallel over t)
// ---------------------------------------------------------------------------
__global__ void prep_kernel(const float* __restrict__ U,
                            const float* __restrict__ W1,
                            const float* __restrict__ b3) {
    const float dt = (float)(5.0 / 60.0);
    int j = threadIdx.x;
    int t = blockIdx.x * blockDim.y + threadIdx.y;
    if (t >= TT) return;
    float d0 = 0.0f;
#pragma unroll
    for (int i = 0; i < HDIM; i++) d0 += W1[j * XDIM + i] * b3[i];
    float acc = dt * d0;
    if (t < TT - 1) {
        const float* u0 = U + t * UDIM;
#pragma unroll
        for (int c = 0; c < UDIM; c++)
            acc += W1[j * XDIM + HDIM + c] * (__ldg(u0 + UDIM + c) - __ldg(u0 + c));
    } else {
        acc = 0.0f;                      // a_TT unused
    }
    g_DV[t * HID + j] = acc;
}

// ---------------------------------------------------------------------------
// Kernel 3: sequential scan over a. 1 CTA, 128 threads (pair-split rows).
// ---------------------------------------------------------------------------
__global__ void __launch_bounds__(128, 1)
scan_kernel(const float* __restrict__ W1,
            const float* __restrict__ b1,
            const float* __restrict__ W2,
            const float* __restrict__ b2,
            const float* __restrict__ U,
            const float* __restrict__ h0) {
    const int j    = threadIdx.x;
    const int unit = j >> 1;
    const int half = j & 1;

    __shared__ __align__(16) float z1s[HID];
    __shared__ __align__(16) float z2s[HID];

    float w2h[32], mrow[32];
#pragma unroll
    for (int m = 0; m < 32; m++) {
        w2h[m]  = W2[unit * HID + 32 * half + m];
        mrow[m] = g_M[unit * HID + 32 * half + m];
    }
    const float b2u = b2[unit];

    // a0 = W1h[unit].h0 + b1[unit] + W1u[unit].u0
    float a = b1[unit];
#pragma unroll
    for (int i = 0; i < HDIM; i++) a += W1[unit * XDIM + i] * h0[i];
#pragma unroll
    for (int c = 0; c < UDIM; c++) a += W1[unit * XDIM + HDIM + c] * U[c];

    float dv = g_DV[unit];
    const float* dvp = g_DV + HID + unit;

#pragma unroll 1
    for (int t = 0; t < TT; t++) {
        float dvn = __ldg(dvp);          // row TT is zero-filled .bss, safe
        dvp += HID;

        // ---- z1 = tanh(a) ----
        float z1 = fast_tanh(a);
        if (!half) z1s[unit] = z1;
        __syncthreads();

        // ---- z2[unit] = tanh(W2[unit].z1 + b2) ; pair-split columns ----
        float c0 = 0.f, c1 = 0.f, c2 = 0.f, c3 = 0.f;
        const float4* z14 = (const float4*)(z1s + 32 * half);
#pragma unroll
        for (int m = 0; m < 8; m += 4) {
            float4 x0 = z14[m], x1 = z14[m + 1], x2 = z14[m + 2], x3 = z14[m + 3];
            c0 += w2h[4*m+0]*x0.x + w2h[4*m+1]*x0.y + w2h[4*m+2]*x0.z + w2h[4*m+3]*x0.w;
            c1 += w2h[4*m+4]*x1.x + w2h[4*m+5]*x1.y + w2h[4*m+6]*x1.z + w2h[4*m+7]*x1.w;
            c2 += w2h[4*m+8]*x2.x + w2h[4*m+9]*x2.y + w2h[4*m+10]*x2.z + w2h[4*m+11]*x2.w;
            c3 += w2h[4*m+12]*x3.x + w2h[4*m+13]*x3.y + w2h[4*m+14]*x3.z + w2h[4*m+15]*x3.w;
        }
        float acc = (c0 + c1) + (c2 + c3);
        acc += __shfl_xor_sync(0xffffffffu, acc, 1);
        float z2 = fast_tanh(acc + b2u);
        if (!half) {
            z2s[unit] = z2;
            g_z2[t * HID + unit] = z2;   // fire-and-forget
        }
        __syncthreads();

        // ---- a += M[unit].z2 + DV_t ----
        float p0 = 0.f, p1 = 0.f, p2 = 0.f, p3 = 0.f;
        const float4* z24 = (const float4*)(z2s + 32 * half);
#pragma unroll
        for (int m = 0; m < 8; m += 4) {
            float4 x0 = z24[m], x1 = z24[m + 1], x2 = z24[m + 2], x3 = z24[m + 3];
            p0 += mrow[4*m+0]*x0.x + mrow[4*m+1]*x0.y + mrow[4*m+2]*x0.z + mrow[4*m+3]*x0.w;
            p1 += mrow[4*m+4]*x1.x + mrow[4*m+5]*x1.y + mrow[4*m+6]*x1.z + mrow[4*m+7]*x1.w;
            p2 += mrow[4*m+8]*x2.x + mrow[4*m+9]*x2.y + mrow[4*m+10]*x2.z + mrow[4*m+11]*x2.w;
            p3 += mrow[4*m+12]*x3.x + mrow[4*m+13]*x3.y + mrow[4*m+14]*x3.z + mrow[4*m+15]*x3.w;
        }
        float p = (p0 + p1) + (p2 + p3);
        p += __shfl_xor_sync(0xffffffffu, p, 1);
        a = (a + dv) + p;
        dv = dvn;
    }
}

// ---------------------------------------------------------------------------
// Kernel 4: sum_t z2_t  ->  g_sumz2   (for hT)
// grid NB x 256 ; tid = r*64 + c
// ---------------------------------------------------------------------------
__global__ void zsum_kernel() {
    int c = threadIdx.x & 63;
    int r = threadIdx.x >> 6;
    int tend = min((int)((blockIdx.x + 1) * CHUNK), TT);
    float acc = 0.0f;
    for (int t = blockIdx.x * CHUNK + r; t < tend; t += 4)
        acc += g_z2[t * HID + c];
    __shared__ float sm[256];
    sm[threadIdx.x] = acc;
    __syncthreads();
    if (threadIdx.x < 64) {
        float s = sm[threadIdx.x] + sm[64 + threadIdx.x] + sm[128 + threadIdx.x] + sm[192 + threadIdx.x];
        atomicAdd(&g_sumz2[threadIdx.x], s);
    }
}

// ---------------------------------------------------------------------------
// Kernel 5: per-t scalars yd/yt/yc = z2_t.r + C, block exclusive scan, totals.
// grid NB x 1024
// ---------------------------------------------------------------------------
__global__ void red_kernel() {
    __shared__ float rs[3 * HID];
    __shared__ float wtot[3][32];
    int tid = threadIdx.x, lane = tid & 31, w = tid >> 5;
    if (tid < 3 * HID) rs[tid] = g_R[tid];
    __syncthreads();

    int t = blockIdx.x * CHUNK + tid;
    float v[3] = {0.f, 0.f, 0.f};
    if (t < TT) {
        const float4* z4 = (const float4*)(g_z2 + t * HID);
#pragma unroll
        for (int k = 0; k < 16; k++) {
            float4 z = z4[k];
#pragma unroll
            for (int s = 0; s < 3; s++) {
                const float* r = rs + s * HID + 4 * k;
                v[s] += z.x * r[0] + z.y * r[1] + z.z * r[2] + z.w * r[3];
            }
        }
#pragma unroll
        for (int s = 0; s < 3; s++) v[s] += g_C[s];
    }

    float inc[3] = {v[0], v[1], v[2]};
#pragma unroll
    for (int d = 1; d < 32; d <<= 1) {
#pragma unroll
        for (int s = 0; s < 3; s++) {
            float n = __shfl_up_sync(0xffffffffu, inc[s], d);
            if (lane >= d) inc[s] += n;
        }
    }
    if (lane == 31)
#pragma unroll
        for (int s = 0; s < 3; s++) wtot[s][w] = inc[s];
    __syncthreads();
    if (w == 0) {
        float x[3];
#pragma unroll
        for (int s = 0; s < 3; s++) x[s] = wtot[s][lane];
#pragma unroll
        for (int d = 1; d < 32; d <<= 1) {
#pragma unroll
            for (int s = 0; s < 3; s++) {
                float n = __shfl_up_sync(0xffffffffu, x[s], d);
                if (lane >= d) x[s] += n;
            }
        }
#pragma unroll
        for (int s = 0; s < 3; s++) wtot[s][lane] = x[s];
    }
    __syncthreads();
#pragma unroll
    for (int s = 0; s < 3; s++) {
        float off = (w > 0) ? wtot[s][w - 1] : 0.0f;
        float excl = off + inc[s] - v[s];
        if (t < TT) g_scan[s][t] = excl;
    }
    if (tid == 0)
#pragma unroll
        for (int s = 0; s < 3; s++) g_btot[s][blockIdx.x] = wtot[s][31];
}

// ---------------------------------------------------------------------------
// Kernel 6: exclusive scan of block totals + hT output. 1 block, 32 threads.
// ---------------------------------------------------------------------------
__global__ void off_kernel(const float* __restrict__ W3,
                           const float* __restrict__ b3,
                           const float* __restrict__ h0,
                           float* __restrict__ out) {
    const float dt = (float)(5.0 / 60.0);
    int tid = threadIdx.x;
    if (tid < 3) {
        float run = 0.0f;
        for (int b = 0; b < NB; b++) {
            g_boff[tid][b] = run;
            run += g_btot[tid][b];
        }
    }
    if (tid < HDIM) {
        float s = 0.0f;
#pragma unroll
        for (int c = 0; c < HID; c++) s += W3[tid * HID + c] * g_sumz2[c];
        out[3 * TT + tid] = h0[tid] + dt * (s + (float)TT * b3[tid]);
    }
}

// ---------------------------------------------------------------------------
// Kernel 7: finalize readouts.  grid NB x 1024
// ---------------------------------------------------------------------------
__global__ void fin_kernel(float* __restrict__ out) {
    int t = blockIdx.x * CHUNK + threadIdx.x;
    if (t >= TT) return;
#pragma unroll
    for (int s = 0; s < 3; s++)
        out[s * TT + t] = g_base[s] + g_boff[s][blockIdx.x] + g_scan[s][t];
}

// ---------------------------------------------------------------------------
extern "C" void kernel_launch(void* const* d_in, const int* in_sizes, int n_in,
                              void* d_out, int out_size) {
    const float* U  = (const float*)d_in[0];
    const float* W1 = (const float*)d_in[1];
    const float* b1 = (const float*)d_in[2];
    const float* W2 = (const float*)d_in[3];
    const float* b2 = (const float*)d_in[4];
    const float* W3 = (const float*)d_in[5];
    const float* b3 = (const float*)d_in[6];
    const float* wd = (const float*)d_in[7];
    const float* bd = (const float*)d_in[8];
    const float* wt = (const float*)d_in[9];
    const float* bt = (const float*)d_in[10];
    const float* wc = (const float*)d_in[11];
    const float* bc = (const float*)d_in[12];
    const float* h0 = (const float*)d_in[13];
    float* out = (float*)d_out;

    const_kernel<<<16, 256>>>(W1, W3, b3, wd, bd, wt, bt, wc, bc, h0);
    dim3 pb(HID, 4);
    prep_kernel<<<(TT + 3) / 4, pb>>>(U, W1, b3);
    scan_kernel<<<1, 128>>>(W1, b1, W2, b2, U, h0);
    zsum_kernel<<<NB, 256>>>();
    red_kernel<<<NB, CHUNK>>>();
    off_kernel<<<1, 32>>>(W3, b3, h0, out);
    fin_kernel<<<NB, CHUNK>>>(out);
}

// round 7
// speedup vs baseline: 1.2381x; 1.0637x over previous
#include <cuda_runtime.h>
#include <cuda_bf16.h>

#define TT    100000
#define HDIM  16
#define UDIM  7
#define HID   64
#define XDIM  (HDIM + UDIM)

// Scratch (static device globals — no runtime allocation).
__device__ float g_V[(TT + 1) * HID];        // V[t][j] = b1[j] + W1_u[j] . u_t
__device__ float g_htraj[(TT + 1) * HDIM];   // h_t trajectory (h_traj[0] = h0)

// branchless tanh: 1 - 2/(e^{2x}+1).  MUFU.EX2 + FADD + MUFU.RCP + FMA. ~1e-6 rel err.
__device__ __forceinline__ float fast_tanh(float x) {
    float e;
    asm("ex2.approx.f32 %0, %1;" : "=f"(e) : "f"(x * 2.8853900817779268f)); // 2*log2(e)
    float r;
    asm("rcp.approx.f32 %0, %1;" : "=f"(r) : "f"(e + 1.0f));
    return fmaf(-2.0f, r, 1.0f);
}

// ---------------------------------------------------------------------------
// Kernel 1: precompute V[t][j] = b1[j] + sum_c W1[j][HDIM+c] * U[t][c]
// Fully parallel over t. blockDim = (64, 4).
// ---------------------------------------------------------------------------
__global__ void pre_kernel(const float* __restrict__ U,
                           const float* __restrict__ W1,
                           const float* __restrict__ b1) {
    int j = threadIdx.x;                       // hidden unit 0..63
    int t = blockIdx.x * blockDim.y + threadIdx.y;
    if (t >= TT) return;
    float acc = b1[j];
    const float* u = U + t * UDIM;
    const float* w = W1 + j * XDIM + HDIM;
#pragma unroll
    for (int c = 0; c < UDIM; c++)
        acc += w[c] * __ldg(u + c);
    g_V[t * HID + j] = acc;
}

// ---------------------------------------------------------------------------
// Kernel 2: the sequential scan. One CTA, 64 threads (2 warps).
// Lane j owns hidden unit j for z1/z2. For dh: i = j>>2, quarter q = j&3.
// Weights register-resident; dt folded into W3/b3.
// ---------------------------------------------------------------------------
__global__ void __launch_bounds__(64, 1)
scan_kernel(const float* __restrict__ W1,
            const float* __restrict__ W2,
            const float* __restrict__ b2,
            const float* __restrict__ W3,
            const float* __restrict__ b3,
            const float* __restrict__ h0,
            float* __restrict__ out) {
    const int j   = threadIdx.x;
    const int q   = j & 3;
    const int i16 = j >> 2;

    __shared__ __align__(16) float z1s[HID];
    __shared__ __align__(16) float z2s[HID];
    __shared__ __align__(16) float hs[HDIM];

    const float dt = (float)(5.0 / 60.0);

    // --- load weights into registers (one-time) ---
    float w1h[HDIM];
#pragma unroll
    for (int c = 0; c < HDIM; c++) w1h[c] = W1[j * XDIM + c];

    float w2r[HID];
#pragma unroll
    for (int c = 0; c < HID; c++) w2r[c] = W2[j * HID + c];
    const float b2j = b2[j];

    float w3q[16];                                // dt pre-folded
#pragma unroll
    for (int m = 0; m < 16; m++) w3q[m] = dt * W3[i16 * HID + q * 16 + m];
    const float b3i = (q == 0) ? dt * b3[i16] : 0.0f;

    float h[HDIM];
#pragma unroll
    for (int c = 0; c < HDIM; c++) h[c] = h0[c];

    if (j < HDIM) g_htraj[j] = h[j];              // h_traj[0] = h0

    const float* vp = g_V + HID + j;              // points at V[t+1][j]
    float vcur = g_V[j];                          // V[0][j]

#pragma unroll 1
    for (int t = 0; t < TT; t++) {
        // prefetch next V early — consumed ~450 cycles later
        float vnext = __ldg(vp);
        vp += HID;

        // ---- z1 = tanh(W1_h . h + V[t][j]) ----
        float a0 = vcur, a1 = 0.f, a2 = 0.f, a3 = 0.f;
#pragma unroll
        for (int c = 0; c < HDIM; c += 4) {
            a0 += w1h[c + 0] * h[c + 0];
            a1 += w1h[c + 1] * h[c + 1];
            a2 += w1h[c + 2] * h[c + 2];
            a3 += w1h[c + 3] * h[c + 3];
        }
        float z1 = fast_tanh((a0 + a1) + (a2 + a3));
        z1s[j] = z1;
        __syncthreads();

        // ---- z2 = tanh(W2 . z1 + b2) ----
        float c0 = b2j, c1 = 0.f, c2 = 0.f, c3 = 0.f;
        const float4* z14 = (const float4*)z1s;
#pragma unroll
        for (int c = 0; c < 16; c++) {
            float4 z = z14[c];
            c0 += w2r[4 * c + 0] * z.x;
            c1 += w2r[4 * c + 1] * z.y;
            c2 += w2r[4 * c + 2] * z.z;
            c3 += w2r[4 * c + 3] * z.w;
        }
        float z2 = fast_tanh((c0 + c1) + (c2 + c3));
        z2s[j] = z2;
        __syncthreads();

        // ---- dh[i16] partial over quarter q (dt folded), 4-lane butterfly ----
        float p0 = 0.f, p1 = 0.f, p2 = 0.f, p3 = 0.f;
        const float4* z24 = (const float4*)(z2s + q * 16);
#pragma unroll
        for (int c = 0; c < 4; c++) {
            float4 z = z24[c];
            p0 += w3q[4 * c + 0] * z.x;
            p1 += w3q[4 * c + 1] * z.y;
            p2 += w3q[4 * c + 2] * z.z;
            p3 += w3q[4 * c + 3] * z.w;
        }
        float p = ((p0 + p1) + (p2 + p3)) + b3i;
        p += __shfl_xor_sync(0xffffffffu, p, 1);
        p += __shfl_xor_sync(0xffffffffu, p, 2);

        if (q == 0) {
            float hn = h[i16] + p;
            hs[i16] = hn;
            g_htraj[(t + 1) * HDIM + i16] = hn;   // fire-and-forget
        }
        __syncthreads();

        // ---- broadcast h back to all lanes ----
        const float4* h4 = (const float4*)hs;
#pragma unroll
        for (int c = 0; c < 4; c++) {
            float4 hv = h4[c];
            h[4 * c + 0] = hv.x;
            h[4 * c + 1] = hv.y;
            h[4 * c + 2] = hv.z;
            h[4 * c + 3] = hv.w;
        }
        vcur = vnext;
    }

    // final state hT -> out[3T .. 3T+16)
    if (j < HDIM) out[3 * TT + j] = h[j];
}

// ---------------------------------------------------------------------------
// Kernel 3: readouts from the stored trajectory. Fully parallel over t.
// ---------------------------------------------------------------------------
__global__ void readout_kernel(const float* __restrict__ wd, const float* __restrict__ bd,
                               const float* __restrict__ wt, const float* __restrict__ bt,
                               const float* __restrict__ wc, const float* __restrict__ bc,
                               float* __restrict__ out) {
    int t = blockIdx.x * blockDim.x + threadIdx.x;
    if (t >= TT) return;

    float vd[HDIM], vt[HDIM], vc[HDIM];
#pragma unroll
    for (int k = 0; k < HDIM; k++) {
        vd[k] = __ldg(wd + k);
        vt[k] = __ldg(wt + k);
        vc[k] = __ldg(wc + k);
    }
    float d = __ldg(bd), x = __ldg(bt), c = __ldg(bc);
    const float4* h4 = (const float4*)(g_htraj + t * HDIM);
#pragma unroll
    for (int k = 0; k < 4; k++) {
        float4 hv = h4[k];
        d += hv.x * vd[4 * k] + hv.y * vd[4 * k + 1] + hv.z * vd[4 * k + 2] + hv.w * vd[4 * k + 3];
        x += hv.x * vt[4 * k] + hv.y * vt[4 * k + 1] + hv.z * vt[4 * k + 2] + hv.w * vt[4 * k + 3];
        c += hv.x * vc[4 * k] + hv.y * vc[4 * k + 1] + hv.z * vc[4 * k + 2] + hv.w * vc[4 * k + 3];
    }
    out[t]          = d;
    out[TT + t]     = x;
    out[2 * TT + t] = c;
}

// ---------------------------------------------------------------------------
extern "C" void kernel_launch(void* const* d_in, const int* in_sizes, int n_in,
                              void* d_out, int out_size) {
    const float* U  = (const float*)d_in[0];
    const float* W1 = (const float*)d_in[1];
    const float* b1 = (const float*)d_in[2];
    const float* W2 = (const float*)d_in[3];
    const float* b2 = (const float*)d_in[4];
    const float* W3 = (const float*)d_in[5];
    const float* b3 = (const float*)d_in[6];
    const float* wd = (const float*)d_in[7];
    const float* bd = (const float*)d_in[8];
    const float* wt = (const float*)d_in[9];
    const float* bt = (const float*)d_in[10];
    const float* wc = (const float*)d_in[11];
    const float* bc = (const float*)d_in[12];
    const float* h0 = (const float*)d_in[13];
    float* out = (float*)d_out;

    dim3 pb(HID, 4);
    pre_kernel<<<(TT + 3) / 4, pb>>>(U, W1, b1);
    scan_kernel<<<1, HID>>>(W1, W2, b2, W3, b3, h0, out);
    readout_kernel<<<(TT + 127) / 128, 128>>>(wd, bd, wt, bt, wc, bc, out);
}